// round 7
// baseline (speedup 1.0000x reference)
#include <cuda_runtime.h>
#include <math.h>

#define HH 160
#define WW 160
#define BB 4
#define CIN 64
#define COUT 64
#define KKK 9
#define PADK 4
#define HWSZ (HH*WW)
#define NPIX (BB*HH*WW)      /* 102400 */
#define EPSV 1e-5f
#define NBLK_A 100           /* 25600 threads / 256 */

// ---------------- device scratch ----------------
__device__ __align__(16) float g_off9[BB*KKK*HH*WW];
__device__ float g_partials[NBLK_A*18];
__device__ float g_scale[KKK];
__device__ float g_shift[KKK];
__device__ __align__(16) float g_wdefT[KKK*CIN*COUT];  // [k][c][o]

// ---------------- packed f32x2 helpers ----------------
__device__ __forceinline__ unsigned long long pack2(float v) {
    unsigned long long r;
    asm("mov.b64 %0, {%1, %1};" : "=l"(r) : "f"(v));
    return r;
}
__device__ __forceinline__ unsigned long long fma2(unsigned long long a,
                                                   unsigned long long b,
                                                   unsigned long long c) {
    unsigned long long d;
    asm("fma.rn.f32x2 %0, %1, %2, %3;" : "=l"(d) : "l"(a), "l"(b), "l"(c));
    return d;
}
__device__ __forceinline__ float2 unpack2(unsigned long long v) {
    float2 f;
    asm("mov.b64 {%0, %1}, %2;" : "=f"(f.x), "=f"(f.y) : "l"(v));
    return f;
}

// ---------------- kernel W: transpose w_def [o][c][k] -> [k][c][o] ----------------
__global__ void transpose_wdef_kernel(const float* __restrict__ w_def) {
    int idx = blockIdx.x*256 + threadIdx.x;
    if (idx >= COUT*CIN*KKK) return;
    int o = idx/(CIN*KKK);
    int c = (idx/KKK)%CIN;
    int k = idx%KKK;
    g_wdefT[(k*CIN + c)*COUT + o] = w_def[idx];
}

// ---------------- kernel A: offset conv (9 odd channels) + partial stats ----------------
__global__ __launch_bounds__(256) void offset_conv_kernel(
        const float* __restrict__ x,
        const float* __restrict__ w_off,
        const float* __restrict__ b_off) {
    __shared__ float wsm[576*12];   // [c*9+ky][ch(9) pad to 12]
    __shared__ float bo[KKK];
    __shared__ float red[8*18];

    int tid = threadIdx.x;
    for (int e = tid; e < 576*9; e += 256) {
        int j = e % 9;
        int ck = e / 9;
        wsm[ck*12 + j] = w_off[(2*j+1)*576 + ck];
    }
    if (tid < 9) bo[tid] = b_off[2*tid+1];
    __syncthreads();

    int g  = blockIdx.x*256 + tid;
    int w4 = g % 40;
    int h  = (g/40) % HH;
    int b  = g / (40*HH);

    float4 acc[9];
#pragma unroll
    for (int j = 0; j < 9; j++) acc[j] = make_float4(bo[j], bo[j], bo[j], bo[j]);

    const float* xb = x + (size_t)b*CIN*HWSZ + w4*4;

#pragma unroll
    for (int ky = 0; ky < 9; ky++) {
        int row = h - PADK + ky;
        if ((unsigned)row >= (unsigned)HH) continue;
        const float* xr = xb + row*WW;
#pragma unroll 4
        for (int c = 0; c < CIN; c++) {
            float4 xv = *(const float4*)(xr + c*HWSZ);
            const float* wr = &wsm[(c*9 + ky)*12];
            float4 wA = *(const float4*)wr;
            float4 wB = *(const float4*)(wr + 4);
            float  w8 = wr[8];
#define FMA4(A, S) { A.x += xv.x*(S); A.y += xv.y*(S); A.z += xv.z*(S); A.w += xv.w*(S); }
            FMA4(acc[0], wA.x); FMA4(acc[1], wA.y); FMA4(acc[2], wA.z); FMA4(acc[3], wA.w);
            FMA4(acc[4], wB.x); FMA4(acc[5], wB.y); FMA4(acc[6], wB.z); FMA4(acc[7], wB.w);
            FMA4(acc[8], w8);
#undef FMA4
        }
    }

#pragma unroll
    for (int j = 0; j < 9; j++) {
        *(float4*)&g_off9[((size_t)(b*9 + j)*HH + h)*WW + w4*4] = acc[j];
    }

    float ls[9], ls2[9];
#pragma unroll
    for (int j = 0; j < 9; j++) {
        float4 a = acc[j];
        ls[j]  = a.x + a.y + a.z + a.w;
        ls2[j] = a.x*a.x + a.y*a.y + a.z*a.z + a.w*a.w;
    }
#pragma unroll
    for (int off = 16; off > 0; off >>= 1) {
#pragma unroll
        for (int j = 0; j < 9; j++) {
            ls[j]  += __shfl_down_sync(0xffffffffu, ls[j],  off);
            ls2[j] += __shfl_down_sync(0xffffffffu, ls2[j], off);
        }
    }
    int lane = tid & 31, wid = tid >> 5;
    if (lane == 0) {
#pragma unroll
        for (int j = 0; j < 9; j++) {
            red[wid*18 + j]     = ls[j];
            red[wid*18 + 9 + j] = ls2[j];
        }
    }
    __syncthreads();
    if (tid < 18) {
        float s = 0.f;
#pragma unroll
        for (int i = 0; i < 8; i++) s += red[i*18 + tid];
        g_partials[blockIdx.x*18 + tid] = s;
    }
}

// ---------------- kernel B: finalize stats ----------------
__global__ void stats_kernel(const float* __restrict__ gamma,
                             const float* __restrict__ beta) {
    __shared__ float sm[18];
    int tid = threadIdx.x;
    if (tid < 18) {
        float s = 0.f;
        for (int i = 0; i < NBLK_A; i++) s += g_partials[i*18 + tid];
        sm[tid] = s;
    }
    __syncthreads();
    if (tid < 9) {
        float mean = sm[tid] * (1.0f/(float)NPIX);
        float var  = sm[9+tid] * (1.0f/(float)NPIX) - mean*mean;
        float rstd = rsqrtf(fmaxf(var, 0.f) + EPSV);
        float sc   = rstd * gamma[2*tid+1];
        g_scale[tid] = sc;
        g_shift[tid] = beta[2*tid+1] - mean*sc;
    }
}

// ---------------- kernel C: deformable conv (pipelined gather, 1 barrier/k) ----------------
// Block = (h, b). Tile 64 o x 160 w. 320 threads: og=tid/40, wg=tid%40 (R2 mapping).
// Samples double-buffered; gather for k+1 interleaved into compute of k.
// Weights read directly from gmem (__ldg, warp-broadcast, L1-hot).
// Smem (floats):
//   s0   [64*160]   sample buffer A                     (40960 B)
//   s1   [64*160]   sample buffer B                     (40960 B)
//   sw01 [9*160]x2  interp weight pairs (float2)        (11520 B)
//   x0s  [9*160]    clamped x0 (short2: a0, a1)         ( 5760 B)
#define SMEM_S0    0
#define SMEM_S1    (64*WW)
#define SMEM_SW01  (2*64*WW)
#define SMEM_A01   (SMEM_SW01 + 2*9*WW)
#define SMEM_TOT_ELEMS (SMEM_A01 + 9*WW)
// = 20480 + 2880 + 1440 = 24800 floats = 99200 B -> 2 blocks/SM

extern __shared__ float dsm[];

__global__ __launch_bounds__(320, 2) void deform_kernel(
        const float* __restrict__ x,
        const float* __restrict__ b_def,
        float* __restrict__ out) {
    float*  s0bf = dsm + SMEM_S0;
    float*  s1bf = dsm + SMEM_S1;
    float2* sw01 = (float2*)(dsm + SMEM_SW01);
    short2* a01  = (short2*)(dsm + SMEM_A01);

    int tid = threadIdx.x;
    int h = blockIdx.x;
    int b = blockIdx.y;

    // ---- phase 0: offsets (tanh + cumulative convert + interp params) ----
    if (tid < WW) {
        int w = tid;
        float y[9], dx[9];
#pragma unroll
        for (int k = 0; k < 9; k++) {
            float v = g_off9[((size_t)(b*9 + k)*HH + h)*WW + w];
            y[k] = tanhf(v*g_scale[k] + g_shift[k]);
        }
        dx[4] = y[4];
        float a = y[4];
#pragma unroll
        for (int k = 3; k >= 0; k--) { a += y[k]; dx[k] = a; }
        a = y[4];
#pragma unroll
        for (int k = 5; k < 9; k++) { a += y[k]; dx[k] = a; }
#pragma unroll
        for (int k = 0; k < 9; k++) {
            float px = (float)w + dx[k];
            float fl = floorf(px);
            float fx = px - fl;
            int   x0 = (int)fl;
            float w0v = (x0 >= 0 && x0 < WW)      ? (1.f - fx) : 0.f;
            float w1v = (x0 >= -1 && x0 < WW - 1) ? fx         : 0.f;
            sw01[k*WW + w] = make_float2(w0v, w1v);
            a01[k*WW + w]  = make_short2((short)min(max(x0,     0), WW - 1),
                                         (short)min(max(x0 + 1, 0), WW - 1));
        }
    }

    const int og = tid / 40;   // 0..7
    const int wg = tid % 40;   // 0..39 -> w = wg*4 .. wg*4+3
    const int gw = tid % WW;   // gather column (0..159)
    const int gc = tid / WW;   // gather channel start (0 or 1)

    unsigned long long acc[4][4];
#pragma unroll
    for (int p = 0; p < 4; p++)
#pragma unroll
        for (int j = 0; j < 4; j++) acc[p][j] = 0ull;

    const float* xbatch = x + (size_t)b*CIN*HWSZ;

    // valid kernel rows: r in [r0, r1], k = r - h + PADK
    int r0 = max(h - PADK, 0);
    int r1 = min(h + PADK, HH - 1);
    int nk = r1 - r0 + 1;
    int k0 = r0 - h + PADK;

    __syncthreads();   // tables ready

    // ---- prologue: gather first k into s0 ----
    {
        const float* xrow = xbatch + (size_t)r0*WW;
        int oidx = k0*WW + gw;
        float2 iw = sw01[oidx];
        short2 aa = a01[oidx];
        const float* p0 = xrow + aa.x;
        const float* p1 = xrow + aa.y;
#pragma unroll 8
        for (int c = gc; c < CIN; c += 2)
            s0bf[c*WW + gw] = iw.x*__ldg(p0 + c*HWSZ) + iw.y*__ldg(p1 + c*HWSZ);
    }

    int buf = 0;
    for (int i = 0; i < nk; i++) {
        int k = k0 + i;
        const float* wkg = g_wdefT + (size_t)k*CIN*COUT + og*8;

        __syncthreads();   // s[buf] complete; s[buf^1] free to overwrite

        float* scur  = buf ? s1bf : s0bf;
        float* snext = buf ? s0bf : s1bf;

        // next-gather params
        bool havenext = (i + 1 < nk);
        float2 iw_n = make_float2(0.f, 0.f);
        const float* p0n = xbatch;
        const float* p1n = xbatch;
        if (havenext) {
            int kn = k + 1;
            int oidx = kn*WW + gw;
            iw_n = sw01[oidx];
            short2 aa = a01[oidx];
            const float* xrow = xbatch + (size_t)(r0 + i + 1)*WW;
            p0n = xrow + aa.x;
            p1n = xrow + aa.y;
        }

        // compute 64 c for k, interleaving 32 gather ops for k+1
#pragma unroll 2
        for (int ii = 0; ii < 32; ii++) {
#pragma unroll
            for (int half = 0; half < 2; half++) {
                int c = 2*ii + half;
                float4 sv = *(const float4*)&scur[c*WW + wg*4];
                unsigned long long sp0 = pack2(sv.x);
                unsigned long long sp1 = pack2(sv.y);
                unsigned long long sp2 = pack2(sv.z);
                unsigned long long sp3 = pack2(sv.w);
                ulonglong2 wA = __ldg((const ulonglong2*)(wkg + c*COUT));
                ulonglong2 wB = __ldg((const ulonglong2*)(wkg + c*COUT + 4));
                acc[0][0] = fma2(wA.x, sp0, acc[0][0]);
                acc[0][1] = fma2(wA.x, sp1, acc[0][1]);
                acc[0][2] = fma2(wA.x, sp2, acc[0][2]);
                acc[0][3] = fma2(wA.x, sp3, acc[0][3]);
                acc[1][0] = fma2(wA.y, sp0, acc[1][0]);
                acc[1][1] = fma2(wA.y, sp1, acc[1][1]);
                acc[1][2] = fma2(wA.y, sp2, acc[1][2]);
                acc[1][3] = fma2(wA.y, sp3, acc[1][3]);
                acc[2][0] = fma2(wB.x, sp0, acc[2][0]);
                acc[2][1] = fma2(wB.x, sp1, acc[2][1]);
                acc[2][2] = fma2(wB.x, sp2, acc[2][2]);
                acc[2][3] = fma2(wB.x, sp3, acc[2][3]);
                acc[3][0] = fma2(wB.y, sp0, acc[3][0]);
                acc[3][1] = fma2(wB.y, sp1, acc[3][1]);
                acc[3][2] = fma2(wB.y, sp2, acc[3][2]);
                acc[3][3] = fma2(wB.y, sp3, acc[3][3]);
            }
            if (havenext) {
                int cg = gc + 2*ii;
                snext[cg*WW + gw] = iw_n.x*__ldg(p0n + cg*HWSZ)
                                  + iw_n.y*__ldg(p1n + cg*HWSZ);
            }
        }
        buf ^= 1;
    }

    // epilogue: unpack o-pairs, add bias, write out
#pragma unroll
    for (int p = 0; p < 4; p++) {
        int o0 = og*8 + 2*p;
        float bv0 = __ldg(&b_def[o0]);
        float bv1 = __ldg(&b_def[o0+1]);
        float2 f0 = unpack2(acc[p][0]);
        float2 f1 = unpack2(acc[p][1]);
        float2 f2 = unpack2(acc[p][2]);
        float2 f3 = unpack2(acc[p][3]);
        float4 q0 = make_float4(f0.x + bv0, f1.x + bv0, f2.x + bv0, f3.x + bv0);
        float4 q1 = make_float4(f0.y + bv1, f1.y + bv1, f2.y + bv1, f3.y + bv1);
        *(float4*)&out[(((size_t)b*COUT + o0  )*HH + h)*WW + wg*4] = q0;
        *(float4*)&out[(((size_t)b*COUT + o0+1)*HH + h)*WW + wg*4] = q1;
    }
}

// ---------------- launch ----------------
extern "C" void kernel_launch(void* const* d_in, const int* in_sizes, int n_in,
                              void* d_out, int out_size) {
    const float* x     = (const float*)d_in[0];
    const float* w_off = (const float*)d_in[1];
    const float* b_off = (const float*)d_in[2];
    const float* gamma = (const float*)d_in[3];
    const float* beta  = (const float*)d_in[4];
    const float* w_def = (const float*)d_in[5];
    const float* b_def = (const float*)d_in[6];
    float* out = (float*)d_out;

    static bool attr_set = false;
    if (!attr_set) {
        cudaFuncSetAttribute(deform_kernel,
                             cudaFuncAttributeMaxDynamicSharedMemorySize,
                             SMEM_TOT_ELEMS * (int)sizeof(float));
        attr_set = true;
    }

    transpose_wdef_kernel<<<(COUT*CIN*KKK + 255)/256, 256>>>(w_def);
    offset_conv_kernel<<<NBLK_A, 256>>>(x, w_off, b_off);
    stats_kernel<<<1, 32>>>(gamma, beta);
    deform_kernel<<<dim3(HH, BB), 320, SMEM_TOT_ELEMS * (int)sizeof(float)>>>(x, b_def, out);
}

// round 8
// speedup vs baseline: 1.0083x; 1.0083x over previous
#include <cuda_runtime.h>
#include <math.h>

#define HH 160
#define WW 160
#define BB 4
#define CIN 64
#define COUT 64
#define KKK 9
#define PADK 4
#define HWSZ (HH*WW)
#define NPIX (BB*HH*WW)      /* 102400 */
#define EPSV 1e-5f
#define NBLK_A 100           /* 25600 threads / 256 */

// ---------------- device scratch ----------------
__device__ __align__(16) float g_off9[BB*KKK*HH*WW];
__device__ float g_partials[NBLK_A*18];
__device__ float g_scale[KKK];
__device__ float g_shift[KKK];
__device__ __align__(16) float g_wdefT[KKK*CIN*COUT];  // [k][c][o]

// ---------------- packed f32x2 helpers ----------------
__device__ __forceinline__ unsigned long long pack2(float v) {
    unsigned long long r;
    asm("mov.b64 %0, {%1, %1};" : "=l"(r) : "f"(v));
    return r;
}
__device__ __forceinline__ unsigned long long fma2(unsigned long long a,
                                                   unsigned long long b,
                                                   unsigned long long c) {
    unsigned long long d;
    asm("fma.rn.f32x2 %0, %1, %2, %3;" : "=l"(d) : "l"(a), "l"(b), "l"(c));
    return d;
}
__device__ __forceinline__ float2 unpack2(unsigned long long v) {
    float2 f;
    asm("mov.b64 {%0, %1}, %2;" : "=f"(f.x), "=f"(f.y) : "l"(v));
    return f;
}

// ---------------- kernel W: transpose w_def [o][c][k] -> [k][c][o] ----------------
__global__ void transpose_wdef_kernel(const float* __restrict__ w_def) {
    int idx = blockIdx.x*256 + threadIdx.x;
    if (idx >= COUT*CIN*KKK) return;
    int o = idx/(CIN*KKK);
    int c = (idx/KKK)%CIN;
    int k = idx%KKK;
    g_wdefT[(k*CIN + c)*COUT + o] = w_def[idx];
}

// ---------------- kernel A: offset conv (9 odd channels) + partial stats ----------------
__global__ __launch_bounds__(256) void offset_conv_kernel(
        const float* __restrict__ x,
        const float* __restrict__ w_off,
        const float* __restrict__ b_off) {
    __shared__ float wsm[576*12];   // [c*9+ky][ch(9) pad to 12]
    __shared__ float bo[KKK];
    __shared__ float red[8*18];

    int tid = threadIdx.x;
    for (int e = tid; e < 576*9; e += 256) {
        int j = e % 9;
        int ck = e / 9;
        wsm[ck*12 + j] = w_off[(2*j+1)*576 + ck];
    }
    if (tid < 9) bo[tid] = b_off[2*tid+1];
    __syncthreads();

    int g  = blockIdx.x*256 + tid;
    int w4 = g % 40;
    int h  = (g/40) % HH;
    int b  = g / (40*HH);

    float4 acc[9];
#pragma unroll
    for (int j = 0; j < 9; j++) acc[j] = make_float4(bo[j], bo[j], bo[j], bo[j]);

    const float* xb = x + (size_t)b*CIN*HWSZ + w4*4;

#pragma unroll
    for (int ky = 0; ky < 9; ky++) {
        int row = h - PADK + ky;
        if ((unsigned)row >= (unsigned)HH) continue;
        const float* xr = xb + row*WW;
#pragma unroll 4
        for (int c = 0; c < CIN; c++) {
            float4 xv = *(const float4*)(xr + c*HWSZ);
            const float* wr = &wsm[(c*9 + ky)*12];
            float4 wA = *(const float4*)wr;
            float4 wB = *(const float4*)(wr + 4);
            float  w8 = wr[8];
#define FMA4(A, S) { A.x += xv.x*(S); A.y += xv.y*(S); A.z += xv.z*(S); A.w += xv.w*(S); }
            FMA4(acc[0], wA.x); FMA4(acc[1], wA.y); FMA4(acc[2], wA.z); FMA4(acc[3], wA.w);
            FMA4(acc[4], wB.x); FMA4(acc[5], wB.y); FMA4(acc[6], wB.z); FMA4(acc[7], wB.w);
            FMA4(acc[8], w8);
#undef FMA4
        }
    }

#pragma unroll
    for (int j = 0; j < 9; j++) {
        *(float4*)&g_off9[((size_t)(b*9 + j)*HH + h)*WW + w4*4] = acc[j];
    }

    float ls[9], ls2[9];
#pragma unroll
    for (int j = 0; j < 9; j++) {
        float4 a = acc[j];
        ls[j]  = a.x + a.y + a.z + a.w;
        ls2[j] = a.x*a.x + a.y*a.y + a.z*a.z + a.w*a.w;
    }
#pragma unroll
    for (int off = 16; off > 0; off >>= 1) {
#pragma unroll
        for (int j = 0; j < 9; j++) {
            ls[j]  += __shfl_down_sync(0xffffffffu, ls[j],  off);
            ls2[j] += __shfl_down_sync(0xffffffffu, ls2[j], off);
        }
    }
    int lane = tid & 31, wid = tid >> 5;
    if (lane == 0) {
#pragma unroll
        for (int j = 0; j < 9; j++) {
            red[wid*18 + j]     = ls[j];
            red[wid*18 + 9 + j] = ls2[j];
        }
    }
    __syncthreads();
    if (tid < 18) {
        float s = 0.f;
#pragma unroll
        for (int i = 0; i < 8; i++) s += red[i*18 + tid];
        g_partials[blockIdx.x*18 + tid] = s;
    }
}

// ---------------- kernel B: finalize stats ----------------
__global__ void stats_kernel(const float* __restrict__ gamma,
                             const float* __restrict__ beta) {
    __shared__ float sm[18];
    int tid = threadIdx.x;
    if (tid < 18) {
        float s = 0.f;
        for (int i = 0; i < NBLK_A; i++) s += g_partials[i*18 + tid];
        sm[tid] = s;
    }
    __syncthreads();
    if (tid < 9) {
        float mean = sm[tid] * (1.0f/(float)NPIX);
        float var  = sm[9+tid] * (1.0f/(float)NPIX) - mean*mean;
        float rstd = rsqrtf(fmaxf(var, 0.f) + EPSV);
        float sc   = rstd * gamma[2*tid+1];
        g_scale[tid] = sc;
        g_shift[tid] = beta[2*tid+1] - mean*sc;
    }
}

// ---------------- kernel C: deformable conv (pipelined gather, 1 barrier/k) ----------------
// Block = (h, b). Tile 64 o x 160 w. 320 threads: og=tid/40, wg=tid%40 (R2 mapping).
// Samples double-buffered; gather for k+1 interleaved into compute of k.
// Weights read directly from gmem (__ldg, warp-broadcast, L1-hot).
// Smem (floats):
//   s0   [64*160]   sample buffer A                     (40960 B)
//   s1   [64*160]   sample buffer B                     (40960 B)
//   sw01 [9*160]x2  interp weight pairs (float2)        (11520 B)
//   x0s  [9*160]    clamped x0 (short2: a0, a1)         ( 5760 B)
#define SMEM_S0    0
#define SMEM_S1    (64*WW)
#define SMEM_SW01  (2*64*WW)
#define SMEM_A01   (SMEM_SW01 + 2*9*WW)
#define SMEM_TOT_ELEMS (SMEM_A01 + 9*WW)
// = 20480 + 2880 + 1440 = 24800 floats = 99200 B -> 2 blocks/SM

extern __shared__ float dsm[];

__global__ __launch_bounds__(320, 2) void deform_kernel(
        const float* __restrict__ x,
        const float* __restrict__ b_def,
        float* __restrict__ out) {
    float*  s0bf = dsm + SMEM_S0;
    float*  s1bf = dsm + SMEM_S1;
    float2* sw01 = (float2*)(dsm + SMEM_SW01);
    short2* a01  = (short2*)(dsm + SMEM_A01);

    int tid = threadIdx.x;
    int h = blockIdx.x;
    int b = blockIdx.y;

    // ---- phase 0: offsets (tanh + cumulative convert + interp params) ----
    if (tid < WW) {
        int w = tid;
        float y[9], dx[9];
#pragma unroll
        for (int k = 0; k < 9; k++) {
            float v = g_off9[((size_t)(b*9 + k)*HH + h)*WW + w];
            y[k] = tanhf(v*g_scale[k] + g_shift[k]);
        }
        dx[4] = y[4];
        float a = y[4];
#pragma unroll
        for (int k = 3; k >= 0; k--) { a += y[k]; dx[k] = a; }
        a = y[4];
#pragma unroll
        for (int k = 5; k < 9; k++) { a += y[k]; dx[k] = a; }
#pragma unroll
        for (int k = 0; k < 9; k++) {
            float px = (float)w + dx[k];
            float fl = floorf(px);
            float fx = px - fl;
            int   x0 = (int)fl;
            float w0v = (x0 >= 0 && x0 < WW)      ? (1.f - fx) : 0.f;
            float w1v = (x0 >= -1 && x0 < WW - 1) ? fx         : 0.f;
            sw01[k*WW + w] = make_float2(w0v, w1v);
            a01[k*WW + w]  = make_short2((short)min(max(x0,     0), WW - 1),
                                         (short)min(max(x0 + 1, 0), WW - 1));
        }
    }

    const int og = tid / 40;   // 0..7
    const int wg = tid % 40;   // 0..39 -> w = wg*4 .. wg*4+3
    const int gw = tid % WW;   // gather column (0..159)
    const int gc = tid / WW;   // gather channel start (0 or 1)

    unsigned long long acc[4][4];
#pragma unroll
    for (int p = 0; p < 4; p++)
#pragma unroll
        for (int j = 0; j < 4; j++) acc[p][j] = 0ull;

    const float* xbatch = x + (size_t)b*CIN*HWSZ;

    // valid kernel rows: r in [r0, r1], k = r - h + PADK
    int r0 = max(h - PADK, 0);
    int r1 = min(h + PADK, HH - 1);
    int nk = r1 - r0 + 1;
    int k0 = r0 - h + PADK;

    __syncthreads();   // tables ready

    // ---- prologue: gather first k into s0 ----
    {
        const float* xrow = xbatch + (size_t)r0*WW;
        int oidx = k0*WW + gw;
        float2 iw = sw01[oidx];
        short2 aa = a01[oidx];
        const float* p0 = xrow + aa.x;
        const float* p1 = xrow + aa.y;
#pragma unroll 8
        for (int c = gc; c < CIN; c += 2)
            s0bf[c*WW + gw] = iw.x*__ldg(p0 + c*HWSZ) + iw.y*__ldg(p1 + c*HWSZ);
    }

    int buf = 0;
    for (int i = 0; i < nk; i++) {
        int k = k0 + i;
        const float* wkg = g_wdefT + (size_t)k*CIN*COUT + og*8;

        __syncthreads();   // s[buf] complete; s[buf^1] free to overwrite

        float* scur  = buf ? s1bf : s0bf;
        float* snext = buf ? s0bf : s1bf;

        // next-gather params
        bool havenext = (i + 1 < nk);
        float2 iw_n = make_float2(0.f, 0.f);
        const float* p0n = xbatch;
        const float* p1n = xbatch;
        if (havenext) {
            int kn = k + 1;
            int oidx = kn*WW + gw;
            iw_n = sw01[oidx];
            short2 aa = a01[oidx];
            const float* xrow = xbatch + (size_t)(r0 + i + 1)*WW;
            p0n = xrow + aa.x;
            p1n = xrow + aa.y;
        }

        // compute 64 c for k, interleaving 32 gather ops for k+1
#pragma unroll 2
        for (int ii = 0; ii < 32; ii++) {
#pragma unroll
            for (int half = 0; half < 2; half++) {
                int c = 2*ii + half;
                float4 sv = *(const float4*)&scur[c*WW + wg*4];
                unsigned long long sp0 = pack2(sv.x);
                unsigned long long sp1 = pack2(sv.y);
                unsigned long long sp2 = pack2(sv.z);
                unsigned long long sp3 = pack2(sv.w);
                ulonglong2 wA = __ldg((const ulonglong2*)(wkg + c*COUT));
                ulonglong2 wB = __ldg((const ulonglong2*)(wkg + c*COUT + 4));
                acc[0][0] = fma2(wA.x, sp0, acc[0][0]);
                acc[0][1] = fma2(wA.x, sp1, acc[0][1]);
                acc[0][2] = fma2(wA.x, sp2, acc[0][2]);
                acc[0][3] = fma2(wA.x, sp3, acc[0][3]);
                acc[1][0] = fma2(wA.y, sp0, acc[1][0]);
                acc[1][1] = fma2(wA.y, sp1, acc[1][1]);
                acc[1][2] = fma2(wA.y, sp2, acc[1][2]);
                acc[1][3] = fma2(wA.y, sp3, acc[1][3]);
                acc[2][0] = fma2(wB.x, sp0, acc[2][0]);
                acc[2][1] = fma2(wB.x, sp1, acc[2][1]);
                acc[2][2] = fma2(wB.x, sp2, acc[2][2]);
                acc[2][3] = fma2(wB.x, sp3, acc[2][3]);
                acc[3][0] = fma2(wB.y, sp0, acc[3][0]);
                acc[3][1] = fma2(wB.y, sp1, acc[3][1]);
                acc[3][2] = fma2(wB.y, sp2, acc[3][2]);
                acc[3][3] = fma2(wB.y, sp3, acc[3][3]);
            }
            if (havenext) {
                int cg = gc + 2*ii;
                snext[cg*WW + gw] = iw_n.x*__ldg(p0n + cg*HWSZ)
                                  + iw_n.y*__ldg(p1n + cg*HWSZ);
            }
        }
        buf ^= 1;
    }

    // epilogue: unpack o-pairs, add bias, write out
#pragma unroll
    for (int p = 0; p < 4; p++) {
        int o0 = og*8 + 2*p;
        float bv0 = __ldg(&b_def[o0]);
        float bv1 = __ldg(&b_def[o0+1]);
        float2 f0 = unpack2(acc[p][0]);
        float2 f1 = unpack2(acc[p][1]);
        float2 f2 = unpack2(acc[p][2]);
        float2 f3 = unpack2(acc[p][3]);
        float4 q0 = make_float4(f0.x + bv0, f1.x + bv0, f2.x + bv0, f3.x + bv0);
        float4 q1 = make_float4(f0.y + bv1, f1.y + bv1, f2.y + bv1, f3.y + bv1);
        *(float4*)&out[(((size_t)b*COUT + o0  )*HH + h)*WW + wg*4] = q0;
        *(float4*)&out[(((size_t)b*COUT + o0+1)*HH + h)*WW + wg*4] = q1;
    }
}

// ---------------- launch ----------------
extern "C" void kernel_launch(void* const* d_in, const int* in_sizes, int n_in,
                              void* d_out, int out_size) {
    const float* x     = (const float*)d_in[0];
    const float* w_off = (const float*)d_in[1];
    const float* b_off = (const float*)d_in[2];
    const float* gamma = (const float*)d_in[3];
    const float* beta  = (const float*)d_in[4];
    const float* w_def = (const float*)d_in[5];
    const float* b_def = (const float*)d_in[6];
    float* out = (float*)d_out;

    static bool attr_set = false;
    if (!attr_set) {
        cudaFuncSetAttribute(deform_kernel,
                             cudaFuncAttributeMaxDynamicSharedMemorySize,
                             SMEM_TOT_ELEMS * (int)sizeof(float));
        attr_set = true;
    }

    transpose_wdef_kernel<<<(COUT*CIN*KKK + 255)/256, 256>>>(w_def);
    offset_conv_kernel<<<NBLK_A, 256>>>(x, w_off, b_off);
    stats_kernel<<<1, 32>>>(gamma, beta);
    deform_kernel<<<dim3(HH, BB), 320, SMEM_TOT_ELEMS * (int)sizeof(float)>>>(x, b_def, out);
}

// round 9
// speedup vs baseline: 1.2160x; 1.2059x over previous
#include <cuda_runtime.h>
#include <math.h>

#define HH 160
#define WW 160
#define BB 4
#define CIN 64
#define COUT 64
#define KKK 9
#define PADK 4
#define HWSZ (HH*WW)
#define NPIX (BB*HH*WW)      /* 102400 */
#define EPSV 1e-5f
#define NBLK_A 100           /* 25600 threads / 256 */

// ---------------- device scratch ----------------
__device__ __align__(16) float g_off9[BB*KKK*HH*WW];
__device__ float g_partials[NBLK_A*18];
__device__ float g_scale[KKK];
__device__ float g_shift[KKK];
__device__ __align__(16) float g_wdefT[KKK*CIN*COUT];  // [k][c][o]

// ---------------- packed f32x2 helpers ----------------
__device__ __forceinline__ unsigned long long pack2(float v) {
    unsigned long long r;
    asm("mov.b64 %0, {%1, %1};" : "=l"(r) : "f"(v));
    return r;
}
__device__ __forceinline__ unsigned long long fma2(unsigned long long a,
                                                   unsigned long long b,
                                                   unsigned long long c) {
    unsigned long long d;
    asm("fma.rn.f32x2 %0, %1, %2, %3;" : "=l"(d) : "l"(a), "l"(b), "l"(c));
    return d;
}
__device__ __forceinline__ unsigned long long add2(unsigned long long a,
                                                   unsigned long long b) {
    unsigned long long d;
    asm("add.rn.f32x2 %0, %1, %2;" : "=l"(d) : "l"(a), "l"(b));
    return d;
}
__device__ __forceinline__ float2 unpack2(unsigned long long v) {
    float2 f;
    asm("mov.b64 {%0, %1}, %2;" : "=f"(f.x), "=f"(f.y) : "l"(v));
    return f;
}

// ---------------- kernel W: transpose w_def [o][c][k] -> [k][c][o] ----------------
__global__ void transpose_wdef_kernel(const float* __restrict__ w_def) {
    int idx = blockIdx.x*256 + threadIdx.x;
    if (idx >= COUT*CIN*KKK) return;
    int o = idx/(CIN*KKK);
    int c = (idx/KKK)%CIN;
    int k = idx%KKK;
    g_wdefT[(k*CIN + c)*COUT + o] = w_def[idx];
}

// ---------------- kernel A: offset conv (9 odd channels) + partial stats ----------------
__global__ __launch_bounds__(256) void offset_conv_kernel(
        const float* __restrict__ x,
        const float* __restrict__ w_off,
        const float* __restrict__ b_off) {
    __shared__ float wsm[576*12];
    __shared__ float bo[KKK];
    __shared__ float red[8*18];

    int tid = threadIdx.x;
    for (int e = tid; e < 576*9; e += 256) {
        int j = e % 9;
        int ck = e / 9;
        wsm[ck*12 + j] = w_off[(2*j+1)*576 + ck];
    }
    if (tid < 9) bo[tid] = b_off[2*tid+1];
    __syncthreads();

    int g  = blockIdx.x*256 + tid;
    int w4 = g % 40;
    int h  = (g/40) % HH;
    int b  = g / (40*HH);

    float4 acc[9];
#pragma unroll
    for (int j = 0; j < 9; j++) acc[j] = make_float4(bo[j], bo[j], bo[j], bo[j]);

    const float* xb = x + (size_t)b*CIN*HWSZ + w4*4;

#pragma unroll
    for (int ky = 0; ky < 9; ky++) {
        int row = h - PADK + ky;
        if ((unsigned)row >= (unsigned)HH) continue;
        const float* xr = xb + row*WW;
#pragma unroll 4
        for (int c = 0; c < CIN; c++) {
            float4 xv = *(const float4*)(xr + c*HWSZ);
            const float* wr = &wsm[(c*9 + ky)*12];
            float4 wA = *(const float4*)wr;
            float4 wB = *(const float4*)(wr + 4);
            float  w8 = wr[8];
#define FMA4(A, S) { A.x += xv.x*(S); A.y += xv.y*(S); A.z += xv.z*(S); A.w += xv.w*(S); }
            FMA4(acc[0], wA.x); FMA4(acc[1], wA.y); FMA4(acc[2], wA.z); FMA4(acc[3], wA.w);
            FMA4(acc[4], wB.x); FMA4(acc[5], wB.y); FMA4(acc[6], wB.z); FMA4(acc[7], wB.w);
            FMA4(acc[8], w8);
#undef FMA4
        }
    }

#pragma unroll
    for (int j = 0; j < 9; j++) {
        *(float4*)&g_off9[((size_t)(b*9 + j)*HH + h)*WW + w4*4] = acc[j];
    }

    float ls[9], ls2[9];
#pragma unroll
    for (int j = 0; j < 9; j++) {
        float4 a = acc[j];
        ls[j]  = a.x + a.y + a.z + a.w;
        ls2[j] = a.x*a.x + a.y*a.y + a.z*a.z + a.w*a.w;
    }
#pragma unroll
    for (int off = 16; off > 0; off >>= 1) {
#pragma unroll
        for (int j = 0; j < 9; j++) {
            ls[j]  += __shfl_down_sync(0xffffffffu, ls[j],  off);
            ls2[j] += __shfl_down_sync(0xffffffffu, ls2[j], off);
        }
    }
    int lane = tid & 31, wid = tid >> 5;
    if (lane == 0) {
#pragma unroll
        for (int j = 0; j < 9; j++) {
            red[wid*18 + j]     = ls[j];
            red[wid*18 + 9 + j] = ls2[j];
        }
    }
    __syncthreads();
    if (tid < 18) {
        float s = 0.f;
#pragma unroll
        for (int i = 0; i < 8; i++) s += red[i*18 + tid];
        g_partials[blockIdx.x*18 + tid] = s;
    }
}

// ---------------- kernel B: finalize stats ----------------
__global__ void stats_kernel(const float* __restrict__ gamma,
                             const float* __restrict__ beta) {
    __shared__ float sm[18];
    int tid = threadIdx.x;
    if (tid < 18) {
        float s = 0.f;
        for (int i = 0; i < NBLK_A; i++) s += g_partials[i*18 + tid];
        sm[tid] = s;
    }
    __syncthreads();
    if (tid < 9) {
        float mean = sm[tid] * (1.0f/(float)NPIX);
        float var  = sm[9+tid] * (1.0f/(float)NPIX) - mean*mean;
        float rstd = rsqrtf(fmaxf(var, 0.f) + EPSV);
        float sc   = rstd * gamma[2*tid+1];
        g_scale[tid] = sc;
        g_shift[tid] = beta[2*tid+1] - mean*sc;
    }
}

// ---------------- kernel C: deformable conv (split-c, 16o x 4w per thread) ----------------
// Block = (h, b). Tile 64 o x 160 w. 320 threads:
//   wg = tid % 40        -> w quad wg*4..wg*4+3
//   og = (tid/40) % 4    -> outputs og*16 .. og*16+15 (warp-uniform)
//   cs = tid / 160       -> channel half cs*32 .. cs*32+31
// Per c: 1 sample LDS.128 feeds 32 FFMA2 (2x R2's ratio).
// Epilogue: cs=1 writes 32 u64 partials into the s buffer; cs=0 adds + stores.
#define SMEM_S     0
#define SMEM_WK    (64*WW)
#define SMEM_SW01  (SMEM_WK + 64*64)            /* float2, in float units */
#define SMEM_A01   (SMEM_SW01 + 2*9*WW)         /* short2, in float units */
#define SMEM_TOT_ELEMS (SMEM_A01 + 9*WW)
// = 10240 + 4096 + 2880 + 1440 = 18656 floats = 74624 B -> 2 blocks/SM

extern __shared__ float dsm[];

__global__ __launch_bounds__(320, 2) void deform_kernel(
        const float* __restrict__ x,
        const float* __restrict__ b_def,
        float* __restrict__ out) {
    float*  s    = dsm + SMEM_S;
    float*  wk   = dsm + SMEM_WK;
    float2* sw01 = (float2*)(dsm + SMEM_SW01);
    short2* a01  = (short2*)(dsm + SMEM_A01);

    int tid = threadIdx.x;
    int h = blockIdx.x;
    int b = blockIdx.y;

    // ---- phase 0: offsets (tanh + cumulative convert + interp params) ----
    if (tid < WW) {
        int w = tid;
        float y[9], dx[9];
#pragma unroll
        for (int k = 0; k < 9; k++) {
            float v = g_off9[((size_t)(b*9 + k)*HH + h)*WW + w];
            y[k] = tanhf(v*g_scale[k] + g_shift[k]);
        }
        dx[4] = y[4];
        float a = y[4];
#pragma unroll
        for (int k = 3; k >= 0; k--) { a += y[k]; dx[k] = a; }
        a = y[4];
#pragma unroll
        for (int k = 5; k < 9; k++) { a += y[k]; dx[k] = a; }
#pragma unroll
        for (int k = 0; k < 9; k++) {
            float px = (float)w + dx[k];
            float fl = floorf(px);
            float fx = px - fl;
            int   x0 = (int)fl;
            float w0v = (x0 >= 0 && x0 < WW)      ? (1.f - fx) : 0.f;
            float w1v = (x0 >= -1 && x0 < WW - 1) ? fx         : 0.f;
            sw01[k*WW + w] = make_float2(w0v, w1v);
            a01[k*WW + w]  = make_short2((short)min(max(x0,     0), WW - 1),
                                         (short)min(max(x0 + 1, 0), WW - 1));
        }
    }

    const int wg = tid % 40;         // 0..39
    const int og = (tid / 40) & 3;   // 0..3 (warp-uniform)
    const int cs = tid / 160;        // 0 or 1
    const int cbase = cs * 32;

    const int gw = tid % WW;         // gather column (0..159)
    const int gc = tid / WW;         // gather channel start (0 or 1)

    // acc[p][j]: o-pair (og*16+2p, og*16+2p+1) at w = wg*4 + j
    unsigned long long acc[8][4];
#pragma unroll
    for (int p = 0; p < 8; p++)
#pragma unroll
        for (int j = 0; j < 4; j++) acc[p][j] = 0ull;

    const float* xbatch = x + (size_t)b*CIN*HWSZ;

    for (int k = 0; k < 9; k++) {
        int row = h - PADK + k;
        if ((unsigned)row >= (unsigned)HH) continue;   // uniform across block
        __syncthreads();  // phase-0 barrier on first valid k / s reuse barrier

        // load w_defT slice for this k
        {
            const float4* wsrc = (const float4*)(g_wdefT + (size_t)k*CIN*COUT);
            float4* wk4 = (float4*)wk;
            for (int i = tid; i < CIN*COUT/4; i += 320) wk4[i] = wsrc[i];
        }
        // gather + interpolate samples s[c][w]; fixed w per thread, stride 2 over c
        {
            const float* xrow = xbatch + (size_t)row*WW;
            int oidx = k*WW + gw;
            float2 iw = sw01[oidx];
            short2 aa = a01[oidx];
            const float* p0 = xrow + aa.x;
            const float* p1 = xrow + aa.y;
#pragma unroll 8
            for (int c = gc; c < CIN; c += 2) {
                s[c*WW + gw] = iw.x*__ldg(p0 + c*HWSZ) + iw.y*__ldg(p1 + c*HWSZ);
            }
        }
        __syncthreads();

        // accumulate over this thread's 32-channel half
#pragma unroll 2
        for (int cc = 0; cc < 32; cc++) {
            int c = cbase + cc;
            float4 sv = *(const float4*)&s[c*WW + wg*4];
            unsigned long long s0 = pack2(sv.x);
            unsigned long long s1 = pack2(sv.y);
            unsigned long long s2 = pack2(sv.z);
            unsigned long long s3 = pack2(sv.w);
            const ulonglong2* wr = (const ulonglong2*)&wk[c*COUT + og*16];
            {
                ulonglong2 wA = wr[0];   // o-pairs 0,1
                ulonglong2 wB = wr[1];   // o-pairs 2,3
                acc[0][0] = fma2(wA.x, s0, acc[0][0]);
                acc[0][1] = fma2(wA.x, s1, acc[0][1]);
                acc[0][2] = fma2(wA.x, s2, acc[0][2]);
                acc[0][3] = fma2(wA.x, s3, acc[0][3]);
                acc[1][0] = fma2(wA.y, s0, acc[1][0]);
                acc[1][1] = fma2(wA.y, s1, acc[1][1]);
                acc[1][2] = fma2(wA.y, s2, acc[1][2]);
                acc[1][3] = fma2(wA.y, s3, acc[1][3]);
                acc[2][0] = fma2(wB.x, s0, acc[2][0]);
                acc[2][1] = fma2(wB.x, s1, acc[2][1]);
                acc[2][2] = fma2(wB.x, s2, acc[2][2]);
                acc[2][3] = fma2(wB.x, s3, acc[2][3]);
                acc[3][0] = fma2(wB.y, s0, acc[3][0]);
                acc[3][1] = fma2(wB.y, s1, acc[3][1]);
                acc[3][2] = fma2(wB.y, s2, acc[3][2]);
                acc[3][3] = fma2(wB.y, s3, acc[3][3]);
            }
            {
                ulonglong2 wC = wr[2];   // o-pairs 4,5
                ulonglong2 wD = wr[3];   // o-pairs 6,7
                acc[4][0] = fma2(wC.x, s0, acc[4][0]);
                acc[4][1] = fma2(wC.x, s1, acc[4][1]);
                acc[4][2] = fma2(wC.x, s2, acc[4][2]);
                acc[4][3] = fma2(wC.x, s3, acc[4][3]);
                acc[5][0] = fma2(wC.y, s0, acc[5][0]);
                acc[5][1] = fma2(wC.y, s1, acc[5][1]);
                acc[5][2] = fma2(wC.y, s2, acc[5][2]);
                acc[5][3] = fma2(wC.y, s3, acc[5][3]);
                acc[6][0] = fma2(wD.x, s0, acc[6][0]);
                acc[6][1] = fma2(wD.x, s1, acc[6][1]);
                acc[6][2] = fma2(wD.x, s2, acc[6][2]);
                acc[6][3] = fma2(wD.x, s3, acc[6][3]);
                acc[7][0] = fma2(wD.y, s0, acc[7][0]);
                acc[7][1] = fma2(wD.y, s1, acc[7][1]);
                acc[7][2] = fma2(wD.y, s2, acc[7][2]);
                acc[7][3] = fma2(wD.y, s3, acc[7][3]);
            }
        }
    }

    // ---- epilogue: combine the two c-halves, add bias, store ----
    __syncthreads();   // s tile dead; reuse as partial buffer
    unsigned long long* part = (unsigned long long*)(dsm + SMEM_S);  // [32][160]
    int t160 = tid % 160;
    if (cs == 1) {
#pragma unroll
        for (int p = 0; p < 8; p++)
#pragma unroll
            for (int j = 0; j < 4; j++)
                part[(p*4 + j)*160 + t160] = acc[p][j];
    }
    __syncthreads();
    if (cs == 0) {
#pragma unroll
        for (int p = 0; p < 8; p++) {
            int o0 = og*16 + 2*p;
            float bv0 = __ldg(&b_def[o0]);
            float bv1 = __ldg(&b_def[o0+1]);
            float2 f[4];
#pragma unroll
            for (int j = 0; j < 4; j++) {
                unsigned long long v = add2(acc[p][j], part[(p*4 + j)*160 + t160]);
                f[j] = unpack2(v);
            }
            float4 q0 = make_float4(f[0].x + bv0, f[1].x + bv0, f[2].x + bv0, f[3].x + bv0);
            float4 q1 = make_float4(f[0].y + bv1, f[1].y + bv1, f[2].y + bv1, f[3].y + bv1);
            *(float4*)&out[(((size_t)b*COUT + o0  )*HH + h)*WW + wg*4] = q0;
            *(float4*)&out[(((size_t)b*COUT + o0+1)*HH + h)*WW + wg*4] = q1;
        }
    }
}

// ---------------- launch ----------------
extern "C" void kernel_launch(void* const* d_in, const int* in_sizes, int n_in,
                              void* d_out, int out_size) {
    const float* x     = (const float*)d_in[0];
    const float* w_off = (const float*)d_in[1];
    const float* b_off = (const float*)d_in[2];
    const float* gamma = (const float*)d_in[3];
    const float* beta  = (const float*)d_in[4];
    const float* w_def = (const float*)d_in[5];
    const float* b_def = (const float*)d_in[6];
    float* out = (float*)d_out;

    static bool attr_set = false;
    if (!attr_set) {
        cudaFuncSetAttribute(deform_kernel,
                             cudaFuncAttributeMaxDynamicSharedMemorySize,
                             SMEM_TOT_ELEMS * (int)sizeof(float));
        attr_set = true;
    }

    transpose_wdef_kernel<<<(COUT*CIN*KKK + 255)/256, 256>>>(w_def);
    offset_conv_kernel<<<NBLK_A, 256>>>(x, w_off, b_off);
    stats_kernel<<<1, 32>>>(gamma, beta);
    deform_kernel<<<dim3(HH, BB), 320, SMEM_TOT_ELEMS * (int)sizeof(float)>>>(x, b_def, out);
}

// round 10
// speedup vs baseline: 1.3052x; 1.0734x over previous
#include <cuda_runtime.h>
#include <math.h>

#define HH 160
#define WW 160
#define BB 4
#define CIN 64
#define COUT 64
#define KKK 9
#define PADK 4
#define HWSZ (HH*WW)
#define NPIX (BB*HH*WW)      /* 102400 */
#define EPSV 1e-5f
#define NBLK_A 100           /* 25600 threads / 256 */
#define WT 80                /* w-tile per block */

// ---------------- device scratch ----------------
__device__ __align__(16) float g_off9[BB*KKK*HH*WW];
__device__ float g_partials[NBLK_A*18];
__device__ float g_scale[KKK];
__device__ float g_shift[KKK];
__device__ __align__(16) float g_wdefT[KKK*CIN*COUT];  // [k][c][o]

// ---------------- packed f32x2 helpers ----------------
__device__ __forceinline__ unsigned long long pack2(float v) {
    unsigned long long r;
    asm("mov.b64 %0, {%1, %1};" : "=l"(r) : "f"(v));
    return r;
}
__device__ __forceinline__ unsigned long long fma2(unsigned long long a,
                                                   unsigned long long b,
                                                   unsigned long long c) {
    unsigned long long d;
    asm("fma.rn.f32x2 %0, %1, %2, %3;" : "=l"(d) : "l"(a), "l"(b), "l"(c));
    return d;
}
__device__ __forceinline__ unsigned long long add2(unsigned long long a,
                                                   unsigned long long b) {
    unsigned long long d;
    asm("add.rn.f32x2 %0, %1, %2;" : "=l"(d) : "l"(a), "l"(b));
    return d;
}
__device__ __forceinline__ float2 unpack2(unsigned long long v) {
    float2 f;
    asm("mov.b64 {%0, %1}, %2;" : "=f"(f.x), "=f"(f.y) : "l"(v));
    return f;
}

// ---------------- kernel W: transpose w_def [o][c][k] -> [k][c][o] ----------------
__global__ void transpose_wdef_kernel(const float* __restrict__ w_def) {
    int idx = blockIdx.x*256 + threadIdx.x;
    if (idx >= COUT*CIN*KKK) return;
    int o = idx/(CIN*KKK);
    int c = (idx/KKK)%CIN;
    int k = idx%KKK;
    g_wdefT[(k*CIN + c)*COUT + o] = w_def[idx];
}

// ---------------- kernel A: offset conv (9 odd channels) + partial stats ----------------
__global__ __launch_bounds__(256) void offset_conv_kernel(
        const float* __restrict__ x,
        const float* __restrict__ w_off,
        const float* __restrict__ b_off) {
    __shared__ float wsm[576*12];
    __shared__ float bo[KKK];
    __shared__ float red[8*18];

    int tid = threadIdx.x;
    for (int e = tid; e < 576*9; e += 256) {
        int j = e % 9;
        int ck = e / 9;
        wsm[ck*12 + j] = w_off[(2*j+1)*576 + ck];
    }
    if (tid < 9) bo[tid] = b_off[2*tid+1];
    __syncthreads();

    int g  = blockIdx.x*256 + tid;
    int w4 = g % 40;
    int h  = (g/40) % HH;
    int b  = g / (40*HH);

    float4 acc[9];
#pragma unroll
    for (int j = 0; j < 9; j++) acc[j] = make_float4(bo[j], bo[j], bo[j], bo[j]);

    const float* xb = x + (size_t)b*CIN*HWSZ + w4*4;

#pragma unroll
    for (int ky = 0; ky < 9; ky++) {
        int row = h - PADK + ky;
        if ((unsigned)row >= (unsigned)HH) continue;
        const float* xr = xb + row*WW;
#pragma unroll 4
        for (int c = 0; c < CIN; c++) {
            float4 xv = *(const float4*)(xr + c*HWSZ);
            const float* wr = &wsm[(c*9 + ky)*12];
            float4 wA = *(const float4*)wr;
            float4 wB = *(const float4*)(wr + 4);
            float  w8 = wr[8];
#define FMA4(A, S) { A.x += xv.x*(S); A.y += xv.y*(S); A.z += xv.z*(S); A.w += xv.w*(S); }
            FMA4(acc[0], wA.x); FMA4(acc[1], wA.y); FMA4(acc[2], wA.z); FMA4(acc[3], wA.w);
            FMA4(acc[4], wB.x); FMA4(acc[5], wB.y); FMA4(acc[6], wB.z); FMA4(acc[7], wB.w);
            FMA4(acc[8], w8);
#undef FMA4
        }
    }

#pragma unroll
    for (int j = 0; j < 9; j++) {
        *(float4*)&g_off9[((size_t)(b*9 + j)*HH + h)*WW + w4*4] = acc[j];
    }

    float ls[9], ls2[9];
#pragma unroll
    for (int j = 0; j < 9; j++) {
        float4 a = acc[j];
        ls[j]  = a.x + a.y + a.z + a.w;
        ls2[j] = a.x*a.x + a.y*a.y + a.z*a.z + a.w*a.w;
    }
#pragma unroll
    for (int off = 16; off > 0; off >>= 1) {
#pragma unroll
        for (int j = 0; j < 9; j++) {
            ls[j]  += __shfl_down_sync(0xffffffffu, ls[j],  off);
            ls2[j] += __shfl_down_sync(0xffffffffu, ls2[j], off);
        }
    }
    int lane = tid & 31, wid = tid >> 5;
    if (lane == 0) {
#pragma unroll
        for (int j = 0; j < 9; j++) {
            red[wid*18 + j]     = ls[j];
            red[wid*18 + 9 + j] = ls2[j];
        }
    }
    __syncthreads();
    if (tid < 18) {
        float s = 0.f;
#pragma unroll
        for (int i = 0; i < 8; i++) s += red[i*18 + tid];
        g_partials[blockIdx.x*18 + tid] = s;
    }
}

// ---------------- kernel B: finalize stats ----------------
__global__ void stats_kernel(const float* __restrict__ gamma,
                             const float* __restrict__ beta) {
    __shared__ float sm[18];
    int tid = threadIdx.x;
    if (tid < 18) {
        float s = 0.f;
        for (int i = 0; i < NBLK_A; i++) s += g_partials[i*18 + tid];
        sm[tid] = s;
    }
    __syncthreads();
    if (tid < 9) {
        float mean = sm[tid] * (1.0f/(float)NPIX);
        float var  = sm[9+tid] * (1.0f/(float)NPIX) - mean*mean;
        float rstd = rsqrtf(fmaxf(var, 0.f) + EPSV);
        float sc   = rstd * gamma[2*tid+1];
        g_scale[tid] = sc;
        g_shift[tid] = beta[2*tid+1] - mean*sc;
    }
}

// ---------------- kernel C: deformable conv (80-w tile, split-c, 3 blk/SM) ----------------
// Block = (h, whalf, b). Tile 64 o x 80 w. 320 threads:
//   wg = tid % 20         -> w quad w0 + wg*4
//   og = (tid / 20) % 8   -> outputs og*8 .. og*8+7
//   cs = tid / 160        -> channel half cs*32 .. cs*32+31
// Thread: 8o x 4w x 32c -> 16 u64 accumulators (32 regs) -> fits 68-reg cap.
// Smem (floats):
//   s    [64*80]   samples for current k    (20480 B)
//   wk   [64*64]   w_defT slice             (16384 B)
//   sw01 [9*80]x2  interp pairs (float2)    ( 5760 B)
//   a01  [9*80]    clamped cols (short2)    ( 2880 B)
#define SMEM_S     0
#define SMEM_WK    (64*WT)
#define SMEM_SW01  (SMEM_WK + 64*64)
#define SMEM_A01   (SMEM_SW01 + 2*9*WT)
#define SMEM_TOT_ELEMS (SMEM_A01 + 9*WT)
// = 5120 + 4096 + 1440 + 720 = 11376 floats = 45504 B -> 3+ blocks/SM

extern __shared__ float dsm[];

__global__ __launch_bounds__(320, 3) void deform_kernel(
        const float* __restrict__ x,
        const float* __restrict__ b_def,
        float* __restrict__ out) {
    float*  s    = dsm + SMEM_S;
    float*  wk   = dsm + SMEM_WK;
    float2* sw01 = (float2*)(dsm + SMEM_SW01);
    short2* a01  = (short2*)(dsm + SMEM_A01);

    int tid = threadIdx.x;
    int h  = blockIdx.x;
    int w0 = blockIdx.y * WT;
    int b  = blockIdx.z;

    // ---- phase 0: offsets (tanh + cumulative convert + interp params) ----
    if (tid < WT) {
        int w = w0 + tid;
        float y[9], dx[9];
#pragma unroll
        for (int k = 0; k < 9; k++) {
            float v = g_off9[((size_t)(b*9 + k)*HH + h)*WW + w];
            y[k] = tanhf(v*g_scale[k] + g_shift[k]);
        }
        dx[4] = y[4];
        float a = y[4];
#pragma unroll
        for (int k = 3; k >= 0; k--) { a += y[k]; dx[k] = a; }
        a = y[4];
#pragma unroll
        for (int k = 5; k < 9; k++) { a += y[k]; dx[k] = a; }
#pragma unroll
        for (int k = 0; k < 9; k++) {
            float px = (float)w + dx[k];
            float fl = floorf(px);
            float fx = px - fl;
            int   x0 = (int)fl;
            float w0v = (x0 >= 0 && x0 < WW)      ? (1.f - fx) : 0.f;
            float w1v = (x0 >= -1 && x0 < WW - 1) ? fx         : 0.f;
            sw01[k*WT + tid] = make_float2(w0v, w1v);
            a01[k*WT + tid]  = make_short2((short)min(max(x0,     0), WW - 1),
                                           (short)min(max(x0 + 1, 0), WW - 1));
        }
    }

    const int wg = tid % 20;          // 0..19
    const int og = (tid / 20) & 7;    // 0..7
    const int cs = tid / 160;         // 0 or 1
    const int cbase = cs * 32;

    const int gw = tid % WT;          // gather column offset (0..79)
    const int gc = tid / WT;          // gather channel start (0..3)

    unsigned long long acc[4][4];
#pragma unroll
    for (int p = 0; p < 4; p++)
#pragma unroll
        for (int j = 0; j < 4; j++) acc[p][j] = 0ull;

    const float* xbatch = x + (size_t)b*CIN*HWSZ;

    for (int k = 0; k < 9; k++) {
        int row = h - PADK + k;
        if ((unsigned)row >= (unsigned)HH) continue;   // uniform across block
        __syncthreads();  // phase-0 barrier on first valid k / s reuse barrier

        // load w_defT slice for this k
        {
            const float4* wsrc = (const float4*)(g_wdefT + (size_t)k*CIN*COUT);
            float4* wk4 = (float4*)wk;
            for (int i = tid; i < CIN*COUT/4; i += 320) wk4[i] = wsrc[i];
        }
        // gather + interpolate samples s[c][gw]; fixed w per thread, stride 4 over c
        {
            const float* xrow = xbatch + (size_t)row*WW;
            int oidx = k*WT + gw;
            float2 iw = sw01[oidx];
            short2 aa = a01[oidx];
            const float* p0 = xrow + aa.x;
            const float* p1 = xrow + aa.y;
#pragma unroll 8
            for (int c = gc; c < CIN; c += 4) {
                s[c*WT + gw] = iw.x*__ldg(p0 + c*HWSZ) + iw.y*__ldg(p1 + c*HWSZ);
            }
        }
        __syncthreads();

        // accumulate over this thread's 32-channel half
#pragma unroll 4
        for (int cc = 0; cc < 32; cc++) {
            int c = cbase + cc;
            float4 sv = *(const float4*)&s[c*WT + wg*4];
            unsigned long long s0 = pack2(sv.x);
            unsigned long long s1 = pack2(sv.y);
            unsigned long long s2 = pack2(sv.z);
            unsigned long long s3 = pack2(sv.w);
            const ulonglong2* wr = (const ulonglong2*)&wk[c*COUT + og*8];
            ulonglong2 wA = wr[0];  // o-pairs (0,1),(2,3)
            ulonglong2 wB = wr[1];  // o-pairs (4,5),(6,7)
            acc[0][0] = fma2(wA.x, s0, acc[0][0]);
            acc[0][1] = fma2(wA.x, s1, acc[0][1]);
            acc[0][2] = fma2(wA.x, s2, acc[0][2]);
            acc[0][3] = fma2(wA.x, s3, acc[0][3]);
            acc[1][0] = fma2(wA.y, s0, acc[1][0]);
            acc[1][1] = fma2(wA.y, s1, acc[1][1]);
            acc[1][2] = fma2(wA.y, s2, acc[1][2]);
            acc[1][3] = fma2(wA.y, s3, acc[1][3]);
            acc[2][0] = fma2(wB.x, s0, acc[2][0]);
            acc[2][1] = fma2(wB.x, s1, acc[2][1]);
            acc[2][2] = fma2(wB.x, s2, acc[2][2]);
            acc[2][3] = fma2(wB.x, s3, acc[2][3]);
            acc[3][0] = fma2(wB.y, s0, acc[3][0]);
            acc[3][1] = fma2(wB.y, s1, acc[3][1]);
            acc[3][2] = fma2(wB.y, s2, acc[3][2]);
            acc[3][3] = fma2(wB.y, s3, acc[3][3]);
        }
    }

    // ---- epilogue: combine c-halves via s buffer, add bias, store ----
    __syncthreads();   // s tile dead; reuse as partial buffer
    unsigned long long* part = (unsigned long long*)(dsm + SMEM_S);  // 160 thr x 16 u64 = 20480 B
    int t160 = tid % 160;
    if (cs == 1) {
#pragma unroll
        for (int p = 0; p < 4; p++)
#pragma unroll
            for (int j = 0; j < 4; j++)
                part[(p*4 + j)*160 + t160] = acc[p][j];
    }
    __syncthreads();
    if (cs == 0) {
#pragma unroll
        for (int p = 0; p < 4; p++) {
            int o0 = og*8 + 2*p;
            float bv0 = __ldg(&b_def[o0]);
            float bv1 = __ldg(&b_def[o0+1]);
            float2 f[4];
#pragma unroll
            for (int j = 0; j < 4; j++) {
                unsigned long long v = add2(acc[p][j], part[(p*4 + j)*160 + t160]);
                f[j] = unpack2(v);
            }
            float4 q0 = make_float4(f[0].x + bv0, f[1].x + bv0, f[2].x + bv0, f[3].x + bv0);
            float4 q1 = make_float4(f[0].y + bv1, f[1].y + bv1, f[2].y + bv1, f[3].y + bv1);
            *(float4*)&out[(((size_t)b*COUT + o0  )*HH + h)*WW + w0 + wg*4] = q0;
            *(float4*)&out[(((size_t)b*COUT + o0+1)*HH + h)*WW + w0 + wg*4] = q1;
        }
    }
}

// ---------------- launch ----------------
extern "C" void kernel_launch(void* const* d_in, const int* in_sizes, int n_in,
                              void* d_out, int out_size) {
    const float* x     = (const float*)d_in[0];
    const float* w_off = (const float*)d_in[1];
    const float* b_off = (const float*)d_in[2];
    const float* gamma = (const float*)d_in[3];
    const float* beta  = (const float*)d_in[4];
    const float* w_def = (const float*)d_in[5];
    const float* b_def = (const float*)d_in[6];
    float* out = (float*)d_out;

    static bool attr_set = false;
    if (!attr_set) {
        cudaFuncSetAttribute(deform_kernel,
                             cudaFuncAttributeMaxDynamicSharedMemorySize,
                             SMEM_TOT_ELEMS * (int)sizeof(float));
        attr_set = true;
    }

    transpose_wdef_kernel<<<(COUT*CIN*KKK + 255)/256, 256>>>(w_def);
    offset_conv_kernel<<<NBLK_A, 256>>>(x, w_off, b_off);
    stats_kernel<<<1, 32>>>(gamma, beta);
    deform_kernel<<<dim3(HH, WW/WT, BB), 320, SMEM_TOT_ELEMS * (int)sizeof(float)>>>(x, b_def, out);
}